// round 15
// baseline (speedup 1.0000x reference)
#include <cuda_runtime.h>

#define BB   32
#define NN   1024
#define WW_  128
#define RR   4
#define SEQ  512
#define DIN  512
#define IFACE 919

// Flattened output offsets (tuple concat order: out, memory, link, usage, prec, ww, rw)
#define OUT_OFF    0ull
#define MEM_OFF    16384ull
#define LINK_OFF   4210688ull
#define USAGE_OFF  37765120ull
#define PREC_OFF   37797888ull
#define WWO_OFF    37830656ull
#define RW_OFF     37863424ull
#define LINK_F4    8388608ull      // 33,554,432 floats / 4

// Static split of the link-zero across the 3 nodes (exact covers, no atomics)
#define Z1_F4      5242880ull      // k1: 2048 blks * 256 thr * 10
#define Z2_F4      2097152ull      // k2: 1024 blks * 256 thr * 8
#define Z3_F4      1048576ull      // k3:  512 blks * 256 thr * 8
#define Z2_OFF     Z1_F4
#define Z3_OFF     (Z1_F4 + Z2_F4)

#define MEAN_BLKS  512
#define ZERO1_BLKS 2048
#define N1_BLKS    (MEAN_BLKS + ZERO1_BLKS)
#define ZERO2_BLKS 1024
#define N2_BLKS    (BB + ZERO2_BLKS)
#define FILL_BLKS  4096
#define ZERO3_BLKS 512
#define N3_BLKS    (FILL_BLKS + ZERO3_BLKS)

// Scratch (no allocations allowed)
__device__ float g_part[32 * BB * DIN];
__device__ float g_er[BB * WW_];
__device__ float g_wv[BB * WW_];

__device__ __forceinline__ float sigmoidf(float x) {
    return 1.0f / (1.0f + expf(-x));
}

__device__ __forceinline__ void pdl_trigger() {
#if __CUDA_ARCH__ >= 900
    cudaTriggerProgrammaticLaunchCompletion();
#endif
}
__device__ __forceinline__ void pdl_wait() {
#if __CUDA_ARCH__ >= 900
    cudaGridDependencySynchronize();
#endif
}

// ---------------------------------------------------------------------------
// Node 1: mean partials of x (33.5MB, DEFAULT cached loads -> x can stay
// L2-resident across replays while the .cs zero sweep recycles its own lines)
// + link-zero chunk 1 (84MB, __stcs, 10 stores/thread).
// ---------------------------------------------------------------------------
__global__ void __launch_bounds__(256)
k1_zero_mean(const float* __restrict__ x, float* __restrict__ out) {
    int bid = blockIdx.x, t = threadIdx.x;
    if (bid < MEAN_BLKS) {
        int b = bid >> 4, c = bid & 15;
        int col = t & 127;          // float4 column (512 floats / 4)
        int h   = t >> 7;           // 16-row half
        int cc  = c * 2 + h;        // chunk-half id in [0, 32)
        const float4* xp = (const float4*)(x + (size_t)b * SEQ * DIN);
        float4 acc = make_float4(0.f, 0.f, 0.f, 0.f);
        int s0 = c * 32 + h * 16;
#pragma unroll
        for (int s = s0; s < s0 + 16; s += 2) {   // 2-way ILP on the loads
            float4 v0 = xp[s * 128 + col];          // default: normal L2 priority
            float4 v1 = xp[(s + 1) * 128 + col];
            acc.x += v0.x + v1.x; acc.y += v0.y + v1.y;
            acc.z += v0.z + v1.z; acc.w += v0.w + v1.w;
        }
        ((float4*)g_part)[(cc * BB + b) * 128 + col] = acc;
        pdl_trigger();              // partials stored -> k2 compute may proceed
    } else {
        pdl_trigger();              // link stores are not a k2 dependency
        float4 z = make_float4(0.f, 0.f, 0.f, 0.f);
        float4* p = (float4*)(out + LINK_OFF);
        size_t base = (size_t)(bid - MEAN_BLKS) * 256 + t;
        size_t stride = (size_t)ZERO1_BLKS * 256;
#pragma unroll
        for (int i = 0; i < 10; i++)            // exact cover of Z1_F4
            __stcs(&p[base + (size_t)i * stride], z);
    }
}

// ---------------------------------------------------------------------------
// Node 2 (PDL on k1): 32 batch-compute blocks (gridDependencySynchronize,
// then combine -> GEMM [645,919) -> activations -> small sections, then
// trigger) + 1024 zero blocks (chunk 2, 34MB; trigger at entry, run
// immediately — overlapping k1's tail).
// ---------------------------------------------------------------------------
__global__ void __launch_bounds__(256)
k2_batch(const float* __restrict__ Wm, float* __restrict__ out) {
    int bid = blockIdx.x, t = threadIdx.x;
    if (bid >= BB) {
        pdl_trigger();              // no one depends on these link stores
        float4 z = make_float4(0.f, 0.f, 0.f, 0.f);
        float4* p = (float4*)(out + LINK_OFF) + Z2_OFF;
        size_t base = (size_t)(bid - BB) * 256 + t;
        size_t stride = (size_t)ZERO2_BLKS * 256;
#pragma unroll
        for (int i = 0; i < 8; i++)             // exact cover of Z2_F4
            __stcs(&p[base + (size_t)i * stride], z);
        return;
    }

    pdl_wait();                     // need k1's g_part
    int b = bid;
    __shared__ float mx[DIN];
    __shared__ float s_rm1[RR], s_fg[RR], s_q[RR];
    __shared__ float s_pw[16];
    __shared__ float s_c1, s_c2, s_u;

    for (int i = t; i < DIN; i += 256) {
        float s = 0.f;
#pragma unroll
        for (int c = 0; c < 32; c++) s += g_part[(c * BB + b) * DIN + i];
        mx[i] = s * (1.0f / 512.0f);
    }
    __syncthreads();

    // iface[j] = mean . W[:,j] for j in [645, 919) only
    float f_loc[2];
    int   j_loc[2];
    int nj = 0;
    for (int j = 645 + t; j < IFACE; j += 256) {
        float acc = 0.f;
#pragma unroll 8
        for (int k = 0; k < DIN; k++) acc = fmaf(mx[k], Wm[k * IFACE + j], acc);
        f_loc[nj] = acc; j_loc[nj] = j; nj++;
    }
    __syncthreads();
    // scatter: mx[0..127]=erase raw, [128..255]=write_vec, [256..259]=free gates,
    // [260]=alloc gate, [261]=write gate, [262..273]=read modes
    for (int i = 0; i < nj; i++) mx[j_loc[i] - 645] = f_loc[i];
    __syncthreads();

    if (t < 128) {
        g_er[b * WW_ + t] = sigmoidf(mx[t]);
        g_wv[b * WW_ + t] = mx[128 + t];
    }
    if (t < RR) {
        float m0 = mx[262 + t], m1 = mx[266 + t], m2 = mx[270 + t];
        float mmax = fmaxf(m0, fmaxf(m1, m2));
        float e0 = expf(m0 - mmax), e1 = expf(m1 - mmax), e2 = expf(m2 - mmax);
        float rm1 = e1 / (e0 + e1 + e2);
        s_rm1[t] = rm1;
        float q = rm1 * (1.0f / 1024.0f);   // exact /2^10
        s_q[t] = q;
        s_fg[t] = sigmoidf(mx[256 + t]);
    }
    __syncthreads();
    if (t == 0) {
        float ret = 1.0f;
#pragma unroll
        for (int r = 0; r < RR; r++) ret *= (1.0f - s_fg[r] * s_q[r]);
        float u = 1e-6f * ret;              // usage (constant over n)
        s_u = u;
        float ag = sigmoidf(mx[260]);
        float wg = sigmoidf(mx[261]);
        s_c1 = wg * ag * (1.0f - u);
        s_c2 = wg * (1.0f - ag) * (1.0f / 1024.0f);
        float sh = 1.0f;                    // exact sequential cumprod prefix
#pragma unroll
        for (int i = 0; i < 16; i++) { s_pw[i] = sh; sh *= u; }
    }
    __syncthreads();

    // out[b, w*4+r] = 1e-6 * rm1[r]   (write-only -> evict-first)
    if (t < 128) {
        float4 ov = make_float4(1e-6f * s_rm1[0], 1e-6f * s_rm1[1],
                                1e-6f * s_rm1[2], 1e-6f * s_rm1[3]);
        __stcs(&((float4*)(out + OUT_OFF))[b * 128 + t], ov);
    }
    // ww (re-read by node 3 -> cached store) / prec / usage / rw (write-only)
    float c1 = s_c1, c2 = s_c2, u = s_u;
    float4 q4 = make_float4(s_q[0], s_q[1], s_q[2], s_q[3]);
#pragma unroll
    for (int n = t; n < NN; n += 256) {
        float shifted = (n < 16) ? s_pw[n] : 0.0f;
        float ww = fmaf(c1, shifted, c2);
        out[WWO_OFF + (size_t)b * NN + n] = ww;              // cached: node 3 re-reads
        __stcs(out + PREC_OFF + (size_t)b * NN + n, ww);
        __stcs(out + USAGE_OFF + (size_t)b * NN + n, u);
        __stcs(&((float4*)(out + RW_OFF))[b * NN + n], q4);
    }
    pdl_trigger();                  // ww/er/wv visible -> k3 fill may proceed
}

// ---------------------------------------------------------------------------
// Node 3 (PDL on k2): memory fill (17MB, 4096 blocks, gridDependencySync) +
// link-zero chunk 3 (17MB, 512 blocks, independent).
// ---------------------------------------------------------------------------
__global__ void __launch_bounds__(256)
k3_mem(float* __restrict__ out) {
    int bid = blockIdx.x, t = threadIdx.x;
    if (bid < FILL_BLKS) {
        pdl_wait();                 // need k2's ww/g_er/g_wv
        int v = bid * 256 + t;                // float4 index into memory
        int b = v >> 15;                      // 32768 f4 per batch
        int rem = v & 32767;
        int n  = rem >> 5;
        int w4 = rem & 31;
        float ww = __ldg(out + WWO_OFF + (size_t)b * NN + n);
        float4 e  = ((const float4*)g_er)[b * 32 + w4];
        float4 wv = ((const float4*)g_wv)[b * 32 + w4];
        float4 m;
        m.x = 1e-6f * (1.0f - ww * e.x) + ww * wv.x;
        m.y = 1e-6f * (1.0f - ww * e.y) + ww * wv.y;
        m.z = 1e-6f * (1.0f - ww * e.z) + ww * wv.z;
        m.w = 1e-6f * (1.0f - ww * e.w) + ww * wv.w;
        __stcs(&((float4*)(out + MEM_OFF))[v], m);
    } else {
        float4 z = make_float4(0.f, 0.f, 0.f, 0.f);
        float4* p = (float4*)(out + LINK_OFF) + Z3_OFF;
        size_t base = (size_t)(bid - FILL_BLKS) * 256 + t;
        size_t stride = (size_t)ZERO3_BLKS * 256;
#pragma unroll
        for (int i = 0; i < 8; i++)             // exact cover of Z3_F4
            __stcs(&p[base + (size_t)i * stride], z);
    }
}

extern "C" void kernel_launch(void* const* d_in, const int* in_sizes, int n_in,
                              void* d_out, int out_size) {
    const float* x  = (const float*)d_in[0];
    const float* Wm = (const float*)d_in[1];
    float* out = (float*)d_out;

    k1_zero_mean<<<N1_BLKS, 256>>>(x, out);

    cudaLaunchAttribute attr;
    attr.id = cudaLaunchAttributeProgrammaticStreamSerialization;
    attr.val.programmaticStreamSerializationAllowed = 1;

    cudaLaunchConfig_t cfg2 = {};
    cfg2.gridDim = dim3(N2_BLKS); cfg2.blockDim = dim3(256);
    cfg2.attrs = &attr; cfg2.numAttrs = 1; cfg2.stream = 0;
    if (cudaLaunchKernelEx(&cfg2, k2_batch, Wm, out) != cudaSuccess)
        k2_batch<<<N2_BLKS, 256>>>(Wm, out);   // PDL-less fallback (sync is no-op)

    cudaLaunchConfig_t cfg3 = {};
    cfg3.gridDim = dim3(N3_BLKS); cfg3.blockDim = dim3(256);
    cfg3.attrs = &attr; cfg3.numAttrs = 1; cfg3.stream = 0;
    if (cudaLaunchKernelEx(&cfg3, k3_mem, out) != cudaSuccess)
        k3_mem<<<N3_BLKS, 256>>>(out);
}

// round 16
// speedup vs baseline: 1.3299x; 1.3299x over previous
#include <cuda_runtime.h>

#define BB   32
#define NN   1024
#define WW_  128
#define RR   4
#define SEQ  512
#define DIN  512
#define IFACE 919

// Flattened output offsets (tuple concat order: out, memory, link, usage, prec, ww, rw)
#define OUT_OFF    0ull
#define MEM_OFF    16384ull
#define LINK_OFF   4210688ull
#define USAGE_OFF  37765120ull
#define PREC_OFF   37797888ull
#define WWO_OFF    37830656ull
#define RW_OFF     37863424ull
#define LINK_F4    8388608ull      // 33,554,432 floats / 4

// Static split of the link-zero across the 3 nodes (exact covers, no atomics)
// 64MB / 34MB / 34MB: k1 keeps the critical path short; k3 overlaps via PDL.
#define Z1_F4      4194304ull      // k1: 2048 blks * 256 thr * 8
#define Z2_F4      2097152ull      // k2: 1024 blks * 256 thr * 8
#define Z3_F4      2097152ull      // k3: 1024 blks * 256 thr * 8
#define Z2_OFF     Z1_F4
#define Z3_OFF     (Z1_F4 + Z2_F4)

#define MEAN_BLKS  512
#define ZERO1_BLKS 2048
#define N1_BLKS    (MEAN_BLKS + ZERO1_BLKS)
#define ZERO2_BLKS 1024
#define N2_BLKS    (BB + ZERO2_BLKS)
#define FILL_BLKS  4096
#define ZERO3_BLKS 1024
#define N3_BLKS    (FILL_BLKS + ZERO3_BLKS)

// Scratch (no allocations allowed)
__device__ float g_part[32 * BB * DIN];
__device__ float g_er[BB * WW_];
__device__ float g_wv[BB * WW_];

__device__ __forceinline__ float sigmoidf(float x) {
    return 1.0f / (1.0f + expf(-x));
}

__device__ __forceinline__ void pdl_trigger() {
#if __CUDA_ARCH__ >= 900
    cudaTriggerProgrammaticLaunchCompletion();
#endif
}
__device__ __forceinline__ void pdl_wait() {
#if __CUDA_ARCH__ >= 900
    cudaGridDependencySynchronize();
#endif
}

// ---------------------------------------------------------------------------
// Node 1: mean partials of x (33.5MB, __ldcs evict-first — proven load-bearing
// in R15's ablation) + link-zero chunk 1 (64MB, __stcs, 8 stores/thread).
// ---------------------------------------------------------------------------
__global__ void __launch_bounds__(256)
k1_zero_mean(const float* __restrict__ x, float* __restrict__ out) {
    int bid = blockIdx.x, t = threadIdx.x;
    if (bid < MEAN_BLKS) {
        int b = bid >> 4, c = bid & 15;
        int col = t & 127;          // float4 column (512 floats / 4)
        int h   = t >> 7;           // 16-row half
        int cc  = c * 2 + h;        // chunk-half id in [0, 32)
        const float4* xp = (const float4*)(x + (size_t)b * SEQ * DIN);
        float4 acc = make_float4(0.f, 0.f, 0.f, 0.f);
        int s0 = c * 32 + h * 16;
#pragma unroll
        for (int s = s0; s < s0 + 16; s += 2) {   // 2-way ILP on the loads
            float4 v0 = __ldcs(&xp[s * 128 + col]);
            float4 v1 = __ldcs(&xp[(s + 1) * 128 + col]);
            acc.x += v0.x + v1.x; acc.y += v0.y + v1.y;
            acc.z += v0.z + v1.z; acc.w += v0.w + v1.w;
        }
        ((float4*)g_part)[(cc * BB + b) * 128 + col] = acc;
        pdl_trigger();              // partials stored -> k2 compute may proceed
    } else {
        pdl_trigger();              // link stores are not a k2 dependency
        float4 z = make_float4(0.f, 0.f, 0.f, 0.f);
        float4* p = (float4*)(out + LINK_OFF);
        size_t base = (size_t)(bid - MEAN_BLKS) * 256 + t;
        size_t stride = (size_t)ZERO1_BLKS * 256;
#pragma unroll
        for (int i = 0; i < 8; i++)             // exact cover of Z1_F4
            __stcs(&p[base + (size_t)i * stride], z);
    }
}

// ---------------------------------------------------------------------------
// Node 2 (PDL on k1): 32 batch-compute blocks (gridDependencySynchronize,
// then combine -> GEMM [645,919) -> activations -> small sections, then
// trigger) + 1024 zero blocks (chunk 2, 34MB; trigger at entry).
// ---------------------------------------------------------------------------
__global__ void __launch_bounds__(256)
k2_batch(const float* __restrict__ Wm, float* __restrict__ out) {
    int bid = blockIdx.x, t = threadIdx.x;
    if (bid >= BB) {
        pdl_trigger();              // no one depends on these link stores
        float4 z = make_float4(0.f, 0.f, 0.f, 0.f);
        float4* p = (float4*)(out + LINK_OFF) + Z2_OFF;
        size_t base = (size_t)(bid - BB) * 256 + t;
        size_t stride = (size_t)ZERO2_BLKS * 256;
#pragma unroll
        for (int i = 0; i < 8; i++)             // exact cover of Z2_F4
            __stcs(&p[base + (size_t)i * stride], z);
        return;
    }

    pdl_wait();                     // need k1's g_part
    int b = bid;
    __shared__ float mx[DIN];
    __shared__ float s_rm1[RR], s_fg[RR], s_q[RR];
    __shared__ float s_pw[16];
    __shared__ float s_c1, s_c2, s_u;

    for (int i = t; i < DIN; i += 256) {
        float s = 0.f;
#pragma unroll
        for (int c = 0; c < 32; c++) s += g_part[(c * BB + b) * DIN + i];
        mx[i] = s * (1.0f / 512.0f);
    }
    __syncthreads();

    // iface[j] = mean . W[:,j] for j in [645, 919) only
    float f_loc[2];
    int   j_loc[2];
    int nj = 0;
    for (int j = 645 + t; j < IFACE; j += 256) {
        float acc = 0.f;
#pragma unroll 8
        for (int k = 0; k < DIN; k++) acc = fmaf(mx[k], Wm[k * IFACE + j], acc);
        f_loc[nj] = acc; j_loc[nj] = j; nj++;
    }
    __syncthreads();
    // scatter: mx[0..127]=erase raw, [128..255]=write_vec, [256..259]=free gates,
    // [260]=alloc gate, [261]=write gate, [262..273]=read modes
    for (int i = 0; i < nj; i++) mx[j_loc[i] - 645] = f_loc[i];
    __syncthreads();

    if (t < 128) {
        g_er[b * WW_ + t] = sigmoidf(mx[t]);
        g_wv[b * WW_ + t] = mx[128 + t];
    }
    if (t < RR) {
        float m0 = mx[262 + t], m1 = mx[266 + t], m2 = mx[270 + t];
        float mmax = fmaxf(m0, fmaxf(m1, m2));
        float e0 = expf(m0 - mmax), e1 = expf(m1 - mmax), e2 = expf(m2 - mmax);
        float rm1 = e1 / (e0 + e1 + e2);
        s_rm1[t] = rm1;
        float q = rm1 * (1.0f / 1024.0f);   // exact /2^10
        s_q[t] = q;
        s_fg[t] = sigmoidf(mx[256 + t]);
    }
    __syncthreads();
    if (t == 0) {
        float ret = 1.0f;
#pragma unroll
        for (int r = 0; r < RR; r++) ret *= (1.0f - s_fg[r] * s_q[r]);
        float u = 1e-6f * ret;              // usage (constant over n)
        s_u = u;
        float ag = sigmoidf(mx[260]);
        float wg = sigmoidf(mx[261]);
        s_c1 = wg * ag * (1.0f - u);
        s_c2 = wg * (1.0f - ag) * (1.0f / 1024.0f);
        float sh = 1.0f;                    // exact sequential cumprod prefix
#pragma unroll
        for (int i = 0; i < 16; i++) { s_pw[i] = sh; sh *= u; }
    }
    __syncthreads();

    // out[b, w*4+r] = 1e-6 * rm1[r]   (write-only -> evict-first)
    if (t < 128) {
        float4 ov = make_float4(1e-6f * s_rm1[0], 1e-6f * s_rm1[1],
                                1e-6f * s_rm1[2], 1e-6f * s_rm1[3]);
        __stcs(&((float4*)(out + OUT_OFF))[b * 128 + t], ov);
    }
    // ww (re-read by node 3 -> cached store) / prec / usage / rw (write-only)
    float c1 = s_c1, c2 = s_c2, u = s_u;
    float4 q4 = make_float4(s_q[0], s_q[1], s_q[2], s_q[3]);
#pragma unroll
    for (int n = t; n < NN; n += 256) {
        float shifted = (n < 16) ? s_pw[n] : 0.0f;
        float ww = fmaf(c1, shifted, c2);
        out[WWO_OFF + (size_t)b * NN + n] = ww;              // cached: node 3 re-reads
        __stcs(out + PREC_OFF + (size_t)b * NN + n, ww);
        __stcs(out + USAGE_OFF + (size_t)b * NN + n, u);
        __stcs(&((float4*)(out + RW_OFF))[b * NN + n], q4);
    }
    pdl_trigger();                  // ww/er/wv visible -> k3 fill may proceed
}

// ---------------------------------------------------------------------------
// Node 3 (PDL on k2): memory fill (17MB, 4096 blocks, gridDependencySync) +
// link-zero chunk 3 (34MB, 1024 blocks, independent).
// ---------------------------------------------------------------------------
__global__ void __launch_bounds__(256)
k3_mem(float* __restrict__ out) {
    int bid = blockIdx.x, t = threadIdx.x;
    if (bid < FILL_BLKS) {
        pdl_wait();                 // need k2's ww/g_er/g_wv
        int v = bid * 256 + t;                // float4 index into memory
        int b = v >> 15;                      // 32768 f4 per batch
        int rem = v & 32767;
        int n  = rem >> 5;
        int w4 = rem & 31;
        float ww = __ldg(out + WWO_OFF + (size_t)b * NN + n);
        float4 e  = ((const float4*)g_er)[b * 32 + w4];
        float4 wv = ((const float4*)g_wv)[b * 32 + w4];
        float4 m;
        m.x = 1e-6f * (1.0f - ww * e.x) + ww * wv.x;
        m.y = 1e-6f * (1.0f - ww * e.y) + ww * wv.y;
        m.z = 1e-6f * (1.0f - ww * e.z) + ww * wv.z;
        m.w = 1e-6f * (1.0f - ww * e.w) + ww * wv.w;
        __stcs(&((float4*)(out + MEM_OFF))[v], m);
    } else {
        float4 z = make_float4(0.f, 0.f, 0.f, 0.f);
        float4* p = (float4*)(out + LINK_OFF) + Z3_OFF;
        size_t base = (size_t)(bid - FILL_BLKS) * 256 + t;
        size_t stride = (size_t)ZERO3_BLKS * 256;
#pragma unroll
        for (int i = 0; i < 8; i++)             // exact cover of Z3_F4
            __stcs(&p[base + (size_t)i * stride], z);
    }
}

extern "C" void kernel_launch(void* const* d_in, const int* in_sizes, int n_in,
                              void* d_out, int out_size) {
    const float* x  = (const float*)d_in[0];
    const float* Wm = (const float*)d_in[1];
    float* out = (float*)d_out;

    k1_zero_mean<<<N1_BLKS, 256>>>(x, out);

    cudaLaunchAttribute attr;
    attr.id = cudaLaunchAttributeProgrammaticStreamSerialization;
    attr.val.programmaticStreamSerializationAllowed = 1;

    cudaLaunchConfig_t cfg2 = {};
    cfg2.gridDim = dim3(N2_BLKS); cfg2.blockDim = dim3(256);
    cfg2.attrs = &attr; cfg2.numAttrs = 1; cfg2.stream = 0;
    if (cudaLaunchKernelEx(&cfg2, k2_batch, Wm, out) != cudaSuccess)
        k2_batch<<<N2_BLKS, 256>>>(Wm, out);   // PDL-less fallback (sync is no-op)

    cudaLaunchConfig_t cfg3 = {};
    cfg3.gridDim = dim3(N3_BLKS); cfg3.blockDim = dim3(256);
    cfg3.attrs = &attr; cfg3.numAttrs = 1; cfg3.stream = 0;
    if (cudaLaunchKernelEx(&cfg3, k3_mem, out) != cudaSuccess)
        k3_mem<<<N3_BLKS, 256>>>(out);
}